// round 15
// baseline (speedup 1.0000x reference)
#include <cuda_runtime.h>
#include <cstdint>

#define B 4
#define N 1024
#define F 256
#define W 32            // 32 x u32 words per 1024-bit row
#define FULL 0xFFFFFFFFu

#define PACK_BLKS 512   // 512 blocks * 8 warps = 4096 rows
#define ZERO_BLKS 1536
#define RANK_BLKS 16
#define TOTAL_BLKS (PACK_BLKS + ZERO_BLKS + RANK_BLKS)
#define MAXK 344        // smem row-cache capacity for a-part (guarded fallback)
#define MAXL 128        // neighbor-list capacity in xp
#define XPB 192         // xp blocks per batch
#define ABLK 8          // a-part blocks per batch
#define RCAP 864        // ranks with SMEM-resident {exc,inc} rows in select

// ---------------- scratch (device globals; no allocations allowed) ----------
__device__ unsigned g_bitsA  [B][N][W];  // adj rows (node space)
__device__ unsigned g_bits1  [B][N][W];  // (adj+I) rows (node space)
__device__ uint2    g_excincR[B][N][W];  // rank-space rows: {exc word, inc word}
__device__ int      g_rank   [B][N];
__device__ int      g_inv    [B][N];
__device__ int      g_perm   [B][N];
__device__ int      g_K      [B];

// Output layout (float32, concatenated):
#define OFF_X   0
#define OFF_P   (B*N*F)
#define OFF_A   (B*N*F + B*N*3)
#define OFF_M   (B*N*F + B*N*3 + B*N*N)
#define NZERO4  ((B*N*F + B*N*3 + B*N*N) / 4)
#define XLINES  ((B*N*F*4)/128)     // 128B lines of x  (32768)
#define PLINES  ((B*N*3*4+127)/128) // 128B lines of pos (384)

// ---------------- K0: pack bitmasks + zero-fill + L2 prefetch + rank --------
__global__ void pack_zero_rank_kernel(const float* __restrict__ adj,
                                      const float* __restrict__ order,
                                      const float* __restrict__ x,
                                      const float* __restrict__ pos,
                                      float* __restrict__ out) {
    if (blockIdx.x >= PACK_BLKS + ZERO_BLKS) {
        // ---- rank: stable sorted position of order[b][i] ----
        int zb = blockIdx.x - (PACK_BLKS + ZERO_BLKS);      // 0..15
        int b = zb >> 2;
        int i = (zb & 3) * 256 + threadIdx.x;
        __shared__ float so[N];
        for (int j = threadIdx.x; j < N; j += 256) so[j] = order[b * N + j];
        __syncthreads();
        float oi = so[i];
        int r = 0;
        const float4* s4 = (const float4*)so;
        #pragma unroll 8
        for (int j4 = 0; j4 < N / 4; ++j4) {
            float4 v = s4[j4];
            int j = j4 * 4;
            r += (v.x < oi) || (v.x == oi && (j + 0) < i);
            r += (v.y < oi) || (v.y == oi && (j + 1) < i);
            r += (v.z < oi) || (v.z == oi && (j + 2) < i);
            r += (v.w < oi) || (v.w == oi && (j + 3) < i);
        }
        g_rank[b][i] = r;
        g_inv[b][r] = i;
        return;
    }
    if (blockIdx.x >= PACK_BLKS) {
        // ---- zero-fill x_p, pos_p, a regions + L2-prefetch x/pos ----
        int zb = blockIdx.x - PACK_BLKS;
        int gt = zb * blockDim.x + threadIdx.x;
        float4 z = make_float4(0.f, 0.f, 0.f, 0.f);
        float4* o = (float4*)out;
        for (int i = gt; i < NZERO4; i += ZERO_BLKS * blockDim.x)
            o[i] = z;
        // warm L2 for the epilogue's latency-bound gathers
        for (int i = gt; i < XLINES; i += ZERO_BLKS * blockDim.x)
            asm volatile("prefetch.global.L2 [%0];"
                         :: "l"((const char*)x + (size_t)i * 128));
        if (gt < PLINES)
            asm volatile("prefetch.global.L2 [%0];"
                         :: "l"((const char*)pos + (size_t)gt * 128));
        return;
    }
    // ---- pack adj rows into bitmasks ----
    int warp = (blockIdx.x * blockDim.x + threadIdx.x) >> 5;   // 0..4095
    int lane = threadIdx.x & 31;
    int b = warp >> 10, i = warp & (N - 1);
    const float4* r4 = (const float4*)(adj + ((size_t)b * N + i) * N) + lane * 8;
    unsigned w = 0;
    #pragma unroll
    for (int j = 0; j < 8; ++j) {
        float4 v = r4[j];
        w |= (v.x != 0.f ? 1u : 0u) << (4 * j)
           | (v.y != 0.f ? 1u : 0u) << (4 * j + 1)
           | (v.z != 0.f ? 1u : 0u) << (4 * j + 2)
           | (v.w != 0.f ? 1u : 0u) << (4 * j + 3);
    }
    g_bitsA[b][i][lane] = w;
    unsigned m1 = w | ((lane == (i >> 5)) ? (1u << (i & 31)) : 0u);
    g_bits1[b][i][lane] = m1;
}

// ---------------- K1: inc rows + permute {exc,inc} into RANK space ----------
__global__ void inc_perm_kernel() {
    int warp = (blockIdx.x * blockDim.x + threadIdx.x) >> 5;
    int lane = threadIdx.x & 31;
    int b = warp >> 10, i = warp & (N - 1);

    unsigned exc = g_bits1[b][i][lane];
    unsigned acc = 0;
    #pragma unroll 4
    for (int w = 0; w < W; ++w) {
        unsigned word = __shfl_sync(FULL, exc, w);
        while (word) {
            int bit = __ffs(word) - 1;
            word &= word - 1;
            acc |= g_bitsA[b][w * 32 + bit][lane];
        }
    }
    // column permutation to rank space
    int sj[32];
    const int4* inv4 = (const int4*)&g_inv[b][0];
    #pragma unroll
    for (int q = 0; q < 8; ++q) {
        int4 v = inv4[lane * 8 + q];
        sj[4 * q] = v.x; sj[4 * q + 1] = v.y; sj[4 * q + 2] = v.z; sj[4 * q + 3] = v.w;
    }
    unsigned excw = 0, incw = 0;
    #pragma unroll
    for (int t = 0; t < 32; ++t) {
        int j = sj[t];
        unsigned ew = __shfl_sync(FULL, exc, j >> 5);
        unsigned iw = __shfl_sync(FULL, acc, j >> 5);
        excw |= ((ew >> (j & 31)) & 1u) << t;
        incw |= ((iw >> (j & 31)) & 1u) << t;
    }
    int r = g_rank[b][i];
    g_excincR[b][r][lane] = make_uint2(excw, incw);
}

// ---------------- K2: serial greedy selection, bulk-copy staging ------------
// dynamic smem: uint2 sEI[RCAP*W] = 864*32*8 = 221184 B
#define SMEM_SEL_BYTES (RCAP * W * 8)
#define BULK_CHUNK (SMEM_SEL_BYTES / 4)       // 55296 B per cp.async.bulk

__device__ __forceinline__ unsigned smem_addr_of(const void* p) {
    unsigned a;
    asm("{ .reg .u64 t; cvta.to.shared.u64 t, %1; cvt.u32.u64 %0, t; }"
        : "=r"(a) : "l"(p));
    return a;
}

__global__ void select_kernel(float* __restrict__ out_mask) {
    extern __shared__ char sm[];
    uint2* sEI = (uint2*)sm;
    __shared__ unsigned snode[W];
    __shared__ __align__(8) unsigned long long mbar;

    int b = blockIdx.x;
    int tid = threadIdx.x;
    unsigned mb = smem_addr_of(&mbar);
    if (tid == 0)
        asm volatile("mbarrier.init.shared.b64 [%0], 1;" :: "r"(mb) : "memory");
    if (tid < W) snode[tid] = 0;
    __syncthreads();
    if (tid >= 32) return;                    // warp 0 runs everything else
    int lane = tid;

    // DMA staging: 4 bulk copies -> one mbarrier (expect_tx = full size)
    if (lane == 0)
        asm volatile("mbarrier.arrive.expect_tx.shared.b64 _, [%0], %1;"
                     :: "r"(mb), "r"((unsigned)SMEM_SEL_BYTES) : "memory");
    __syncwarp();
    if (lane < 4) {
        unsigned dst = smem_addr_of(sm) + lane * BULK_CHUNK;
        const char* src = (const char*)&g_excincR[b][0][0] + (size_t)lane * BULK_CHUNK;
        asm volatile(
            "cp.async.bulk.shared::cluster.global.mbarrier::complete_tx::bytes "
            "[%0], [%1], %2, [%3];"
            :: "r"(dst), "l"(src), "r"((unsigned)BULK_CHUNK), "r"(mb) : "memory");
    }
    // wait for staging completion (phase 0)
    asm volatile(
        "{\n\t.reg .pred P;\n\t"
        "W0:\n\t"
        "mbarrier.try_wait.parity.shared.b64 P, [%0], 0;\n\t"
        "@!P bra W0;\n\t}"
        :: "r"(mb) : "memory");

    unsigned av = FULL;                       // node_mask all-true
    unsigned sel = 0;                         // rank-space selected set
    unsigned fr = (lane == 0) ? 1u : 0u;      // initial frontier = rank 0
    int r = 0;

    int guard = 0;
    while (guard++ < 2 * N) {
        sel |= (lane == (r >> 5)) ? (1u << (r & 31)) : 0u;
        uint2 ei = (r < RCAP) ? sEI[(r << 5) + lane]    // one LDS.64
                              : g_excincR[b][r][lane];  // rare high-rank fallback
        av &= ~ei.x;                          // exc includes self bit
        fr = (fr | ei.y) & av;
        // branchless: key < N -> frontier pick; N<=key<2N -> restart pick; 2N -> done
        int key = fr ? ((lane << 5) + __ffs(fr) - 1)
                     : (av ? ((lane << 5) + __ffs(av) - 1 + N) : 2 * N);
        key = __reduce_min_sync(FULL, key);
        if (key >= 2 * N) break;              // av empty -> done
        bool restart = key >= N;
        fr = restart ? av : fr;
        r  = restart ? key - N : key;
    }

    // convert rank-space sel to node space
    unsigned m = sel;
    while (m) {
        int t = __ffs(m) - 1;
        m &= m - 1;
        int node = g_inv[b][lane * 32 + t];
        atomicOr(&snode[node >> 5], 1u << (node & 31));
    }
    __syncwarp();
    unsigned selN = snode[lane];

    // stable top_k permutation: selected ascending, then unselected ascending
    int cnt = __popc(selN);
    int v = cnt;
    #pragma unroll
    for (int o = 1; o < 32; o <<= 1) {
        int n2 = __shfl_up_sync(FULL, v, o);
        if (lane >= o) v += n2;
    }
    int K = __shfl_sync(FULL, v, 31);
    int selpos = v - cnt;
    int unspos = K + (lane * 32 - selpos);
    #pragma unroll
    for (int i = 0; i < 32; ++i) {
        int node = lane * 32 + i;
        if ((selN >> i) & 1u) g_perm[b][selpos++] = node;
        else                  g_perm[b][unspos++] = node;
    }
    if (lane == 0) g_K[b] = K;
    #pragma unroll
    for (int w = 0; w < W; ++w) {
        int j = w * 32 + lane;
        out_mask[b * N + j] = (j < K) ? 1.0f : 0.0f;
    }
}

// ---------------- K3: fused epilogue: x_p + pos_p (blocks<XPB), a (rest) ----
__global__ void epilogue_kernel(const float* __restrict__ x, const float* __restrict__ pos,
                                float* __restrict__ out_x, float* __restrict__ out_pos,
                                float* __restrict__ out_a) {
    int b = blockIdx.y;
    int K = g_K[b];
    int tid = threadIdx.x;

    if (blockIdx.x >= XPB) {
        // ================= a-part: coarsened adjacency =================
        int ablk = blockIdx.x - XPB;          // 0..ABLK-1
        __shared__ unsigned srows[MAXK][33];
        __shared__ int sperm[MAXK];
        int KC = K < MAXK ? K : MAXK;
        for (int j = tid; j < KC; j += 256) sperm[j] = g_perm[b][j];
        __syncthreads();
        for (int t = tid; t < KC * W; t += 256) {
            int j = t >> 5, w = t & 31;
            srows[j][w] = g_bitsA[b][sperm[j]][w];
        }
        __syncthreads();
        for (int i = ablk; i < K; i += ABLK) {
            int pi = (i < KC) ? sperm[i] : g_perm[b][i];
            const unsigned* ri = (i < KC) ? &srows[i][0] : &g_bitsA[b][pi][0];
            for (int j = tid; j < K; j += 256) {
                const unsigned* rj = (j < KC) ? &srows[j][0] : &g_bitsA[b][g_perm[b][j]][0];
                int s = 0;
                #pragma unroll
                for (int w = 0; w < W; ++w) s += __popc(ri[w] & rj[w]);
                s += (rj[pi >> 5] >> (pi & 31)) & 1;   // diagonal self-term of (A+I)@A
                out_a[((size_t)b * N + i) * N + j] = (float)s;
            }
        }
        return;
    }

    // ================= xp-part: pooled x and pos =================
    int f = tid;                               // 256 threads == F
    __shared__ int spk, snn;
    __shared__ int list[MAXL];
    for (int k = blockIdx.x; k < K; k += XPB) {
        if (f == 0) spk = g_perm[b][k];
        __syncthreads();
        if (f < 32) {
            unsigned wd = g_bits1[b][spk][f];
            int c = __popc(wd);
            int v = c;
            #pragma unroll
            for (int o = 1; o < 32; o <<= 1) {
                int t = __shfl_up_sync(FULL, v, o);
                if (f >= o) v += t;
            }
            int p = v - c;
            while (wd) {
                int bt = __ffs(wd) - 1;
                wd &= wd - 1;
                list[p++] = f * 32 + bt;
            }
            if (f == 31) snn = v;
        }
        __syncthreads();
        int nn = snn;

        // dual accumulators: 16 outstanding loads per thread
        float acc0 = 0.0f, acc1 = 0.0f;
        int i = 0;
        #pragma unroll 8
        for (; i + 1 < nn; i += 2) {
            acc0 += __ldg(&x[((size_t)b * N + list[i])     * F + f]);
            acc1 += __ldg(&x[((size_t)b * N + list[i + 1]) * F + f]);
        }
        if (i < nn) acc0 += __ldg(&x[((size_t)b * N + list[i]) * F + f]);
        out_x[((size_t)b * N + k) * F + f] = acc0 + acc1;

        // pos: 3 warps, warp c sums coordinate c with lane-strided gathers
        if (f < 96) {
            int c = f >> 5, l = f & 31;
            float p = 0.0f;
            for (int i2 = l; i2 < nn; i2 += 32)
                p += __ldg(&pos[((size_t)b * N + list[i2]) * 3 + c]);
            #pragma unroll
            for (int o = 16; o; o >>= 1) p += __shfl_xor_sync(FULL, p, o);
            if (l == 0) out_pos[((size_t)b * N + k) * 3 + c] = p / (float)nn;
        }
        __syncthreads();
    }
}

// ---------------- launch ----------------------------------------------------
extern "C" void kernel_launch(void* const* d_in, const int* in_sizes, int n_in,
                              void* d_out, int out_size) {
    const float *x = nullptr, *adj = nullptr, *pos = nullptr, *order = nullptr;
    for (int i = 0; i < n_in; ++i) {
        if      (in_sizes[i] == B * N * N) adj   = (const float*)d_in[i];
        else if (in_sizes[i] == B * N * F) x     = (const float*)d_in[i];
        else if (in_sizes[i] == B * N * 3) pos   = (const float*)d_in[i];
        else if (in_sizes[i] == B * N) { if (!order) order = (const float*)d_in[i]; }
    }
    float* out = (float*)d_out;

    cudaFuncSetAttribute(select_kernel,
                         cudaFuncAttributeMaxDynamicSharedMemorySize, SMEM_SEL_BYTES);

    pack_zero_rank_kernel<<<TOTAL_BLKS, 256>>>(adj, order, x, pos, out);
    inc_perm_kernel      <<<(B * N) / 8, 256>>>();
    select_kernel        <<<B, 256, SMEM_SEL_BYTES>>>(out + OFF_M);
    {
        dim3 g(XPB + ABLK, B);
        epilogue_kernel<<<g, 256>>>(x, pos, out + OFF_X, out + OFF_P, out + OFF_A);
    }
}

// round 16
// speedup vs baseline: 1.0052x; 1.0052x over previous
#include <cuda_runtime.h>
#include <cstdint>

#define B 4
#define N 1024
#define F 256
#define W 32            // 32 x u32 words per 1024-bit row
#define FULL 0xFFFFFFFFu

#define PACK_BLKS 512   // 512 blocks * 8 warps = 4096 rows
#define ZERO_BLKS 1536
#define RANK_BLKS 16
#define TOTAL_BLKS (PACK_BLKS + ZERO_BLKS + RANK_BLKS)
#define MAXK 344        // smem row-cache capacity for a_kernel (guarded fallback)
#define MAXL 128        // neighbor-list capacity in xp
#define DMAL 64         // rows DMA-gathered to smem in xp (fallback above)
#define XPB 192         // xp blocks per batch
#define ABLK2 32        // a_kernel blocks per batch
#define RCAP 864        // ranks with SMEM-resident {exc,inc} rows in select

// ---------------- scratch (device globals; no allocations allowed) ----------
__device__ unsigned g_bitsA  [B][N][W];  // adj rows (node space)
__device__ unsigned g_bits1  [B][N][W];  // (adj+I) rows (node space)
__device__ uint2    g_excincR[B][N][W];  // rank-space rows: {exc word, inc word}
__device__ int      g_rank   [B][N];
__device__ int      g_inv    [B][N];
__device__ int      g_perm   [B][N];
__device__ int      g_K      [B];

// Output layout (float32, concatenated):
#define OFF_X   0
#define OFF_P   (B*N*F)
#define OFF_A   (B*N*F + B*N*3)
#define OFF_M   (B*N*F + B*N*3 + B*N*N)
#define NZERO4  ((B*N*F + B*N*3 + B*N*N) / 4)

__device__ __forceinline__ unsigned smem_addr_of(const void* p) {
    unsigned a;
    asm("{ .reg .u64 t; cvta.to.shared.u64 t, %1; cvt.u32.u64 %0, t; }"
        : "=r"(a) : "l"(p));
    return a;
}

// ---------------- K0: pack bitmasks + zero-fill outputs + rank (fused) ------
__global__ void pack_zero_rank_kernel(const float* __restrict__ adj,
                                      const float* __restrict__ order,
                                      float* __restrict__ out) {
    if (blockIdx.x >= PACK_BLKS + ZERO_BLKS) {
        // ---- rank: stable sorted position of order[b][i] ----
        int zb = blockIdx.x - (PACK_BLKS + ZERO_BLKS);      // 0..15
        int b = zb >> 2;
        int i = (zb & 3) * 256 + threadIdx.x;
        __shared__ float so[N];
        for (int j = threadIdx.x; j < N; j += 256) so[j] = order[b * N + j];
        __syncthreads();
        float oi = so[i];
        int r = 0;
        const float4* s4 = (const float4*)so;
        #pragma unroll 8
        for (int j4 = 0; j4 < N / 4; ++j4) {
            float4 v = s4[j4];
            int j = j4 * 4;
            r += (v.x < oi) || (v.x == oi && (j + 0) < i);
            r += (v.y < oi) || (v.y == oi && (j + 1) < i);
            r += (v.z < oi) || (v.z == oi && (j + 2) < i);
            r += (v.w < oi) || (v.w == oi && (j + 3) < i);
        }
        g_rank[b][i] = r;
        g_inv[b][r] = i;
        return;
    }
    if (blockIdx.x >= PACK_BLKS) {
        // ---- zero-fill x_p, pos_p, a regions ----
        int zb = blockIdx.x - PACK_BLKS;
        float4 z = make_float4(0.f, 0.f, 0.f, 0.f);
        float4* o = (float4*)out;
        for (int i = zb * blockDim.x + threadIdx.x; i < NZERO4; i += ZERO_BLKS * blockDim.x)
            o[i] = z;
        return;
    }
    // ---- pack adj rows into bitmasks ----
    int warp = (blockIdx.x * blockDim.x + threadIdx.x) >> 5;   // 0..4095
    int lane = threadIdx.x & 31;
    int b = warp >> 10, i = warp & (N - 1);
    const float4* r4 = (const float4*)(adj + ((size_t)b * N + i) * N) + lane * 8;
    unsigned w = 0;
    #pragma unroll
    for (int j = 0; j < 8; ++j) {
        float4 v = r4[j];
        w |= (v.x != 0.f ? 1u : 0u) << (4 * j)
           | (v.y != 0.f ? 1u : 0u) << (4 * j + 1)
           | (v.z != 0.f ? 1u : 0u) << (4 * j + 2)
           | (v.w != 0.f ? 1u : 0u) << (4 * j + 3);
    }
    g_bitsA[b][i][lane] = w;
    unsigned m1 = w | ((lane == (i >> 5)) ? (1u << (i & 31)) : 0u);
    g_bits1[b][i][lane] = m1;
}

// ---------------- K1: inc rows + permute {exc,inc} into RANK space ----------
__global__ void inc_perm_kernel() {
    int warp = (blockIdx.x * blockDim.x + threadIdx.x) >> 5;
    int lane = threadIdx.x & 31;
    int b = warp >> 10, i = warp & (N - 1);

    unsigned exc = g_bits1[b][i][lane];
    unsigned acc = 0;
    #pragma unroll 4
    for (int w = 0; w < W; ++w) {
        unsigned word = __shfl_sync(FULL, exc, w);
        while (word) {
            int bit = __ffs(word) - 1;
            word &= word - 1;
            acc |= g_bitsA[b][w * 32 + bit][lane];
        }
    }
    // column permutation to rank space
    int sj[32];
    const int4* inv4 = (const int4*)&g_inv[b][0];
    #pragma unroll
    for (int q = 0; q < 8; ++q) {
        int4 v = inv4[lane * 8 + q];
        sj[4 * q] = v.x; sj[4 * q + 1] = v.y; sj[4 * q + 2] = v.z; sj[4 * q + 3] = v.w;
    }
    unsigned excw = 0, incw = 0;
    #pragma unroll
    for (int t = 0; t < 32; ++t) {
        int j = sj[t];
        unsigned ew = __shfl_sync(FULL, exc, j >> 5);
        unsigned iw = __shfl_sync(FULL, acc, j >> 5);
        excw |= ((ew >> (j & 31)) & 1u) << t;
        incw |= ((iw >> (j & 31)) & 1u) << t;
    }
    int r = g_rank[b][i];
    g_excincR[b][r][lane] = make_uint2(excw, incw);
}

// ---------------- K2: serial greedy selection, bulk-copy staging ------------
// dynamic smem: uint2 sEI[RCAP*W] = 864*32*8 = 221184 B
#define SMEM_SEL_BYTES (RCAP * W * 8)
#define BULK_CHUNK (SMEM_SEL_BYTES / 4)       // 55296 B per cp.async.bulk

__global__ void select_kernel(float* __restrict__ out_mask) {
    extern __shared__ char sm[];
    uint2* sEI = (uint2*)sm;
    __shared__ unsigned snode[W];
    __shared__ __align__(8) unsigned long long mbar;

    int b = blockIdx.x;
    int tid = threadIdx.x;
    unsigned mb = smem_addr_of(&mbar);
    if (tid == 0)
        asm volatile("mbarrier.init.shared.b64 [%0], 1;" :: "r"(mb) : "memory");
    if (tid < W) snode[tid] = 0;
    __syncthreads();
    if (tid >= 32) return;                    // warp 0 runs everything else
    int lane = tid;

    // DMA staging: 4 bulk copies -> one mbarrier (expect_tx = full size)
    if (lane == 0)
        asm volatile("mbarrier.arrive.expect_tx.shared.b64 _, [%0], %1;"
                     :: "r"(mb), "r"((unsigned)SMEM_SEL_BYTES) : "memory");
    __syncwarp();
    if (lane < 4) {
        unsigned dst = smem_addr_of(sm) + lane * BULK_CHUNK;
        const char* src = (const char*)&g_excincR[b][0][0] + (size_t)lane * BULK_CHUNK;
        asm volatile(
            "cp.async.bulk.shared::cluster.global.mbarrier::complete_tx::bytes "
            "[%0], [%1], %2, [%3];"
            :: "r"(dst), "l"(src), "r"((unsigned)BULK_CHUNK), "r"(mb) : "memory");
    }
    // wait for staging completion (phase 0)
    asm volatile(
        "{\n\t.reg .pred P;\n\t"
        "W0:\n\t"
        "mbarrier.try_wait.parity.shared.b64 P, [%0], 0;\n\t"
        "@!P bra W0;\n\t}"
        :: "r"(mb) : "memory");

    unsigned av = FULL;                       // node_mask all-true
    unsigned sel = 0;                         // rank-space selected set
    unsigned fr = (lane == 0) ? 1u : 0u;      // initial frontier = rank 0
    int r = 0;

    int guard = 0;
    while (guard++ < 2 * N) {
        sel |= (lane == (r >> 5)) ? (1u << (r & 31)) : 0u;
        uint2 ei = (r < RCAP) ? sEI[(r << 5) + lane]    // one LDS.64
                              : g_excincR[b][r][lane];  // rare high-rank fallback
        av &= ~ei.x;                          // exc includes self bit
        fr = (fr | ei.y) & av;
        // branchless: key < N -> frontier pick; N<=key<2N -> restart pick; 2N -> done
        int key = fr ? ((lane << 5) + __ffs(fr) - 1)
                     : (av ? ((lane << 5) + __ffs(av) - 1 + N) : 2 * N);
        key = __reduce_min_sync(FULL, key);
        if (key >= 2 * N) break;              // av empty -> done
        bool restart = key >= N;
        fr = restart ? av : fr;
        r  = restart ? key - N : key;
    }

    // convert rank-space sel to node space
    unsigned m = sel;
    while (m) {
        int t = __ffs(m) - 1;
        m &= m - 1;
        int node = g_inv[b][lane * 32 + t];
        atomicOr(&snode[node >> 5], 1u << (node & 31));
    }
    __syncwarp();
    unsigned selN = snode[lane];

    // stable top_k permutation: selected ascending, then unselected ascending
    int cnt = __popc(selN);
    int v = cnt;
    #pragma unroll
    for (int o = 1; o < 32; o <<= 1) {
        int n2 = __shfl_up_sync(FULL, v, o);
        if (lane >= o) v += n2;
    }
    int K = __shfl_sync(FULL, v, 31);
    int selpos = v - cnt;
    int unspos = K + (lane * 32 - selpos);
    #pragma unroll
    for (int i = 0; i < 32; ++i) {
        int node = lane * 32 + i;
        if ((selN >> i) & 1u) g_perm[b][selpos++] = node;
        else                  g_perm[b][unspos++] = node;
    }
    if (lane == 0) g_K[b] = K;
    #pragma unroll
    for (int w = 0; w < W; ++w) {
        int j = w * 32 + lane;
        out_mask[b * N + j] = (j < K) ? 1.0f : 0.0f;
    }
}

// ---------------- K3: x_p + pos_p via DMA row gather ------------------------
// dynamic smem layout:
//   [0)       float sx[DMAL][F]      65536 B
//   [65536)   int   list[MAXL]         512 B
//   [66048)   u64   mbar                 8 B
#define SMEM_XP_BYTES (65536 + 512 + 16)

__global__ void xp_kernel(const float* __restrict__ x, const float* __restrict__ pos,
                          float* __restrict__ out_x, float* __restrict__ out_pos) {
    extern __shared__ char sm[];
    float* sx  = (float*)sm;
    int* list  = (int*)(sm + 65536);
    unsigned mb = smem_addr_of(sm + 66048);
    __shared__ int snn;

    int b = blockIdx.y;
    int K = g_K[b];
    int tid = threadIdx.x;
    if (tid == 0)
        asm volatile("mbarrier.init.shared.b64 [%0], 1;" :: "r"(mb) : "memory");
    __syncthreads();
    int par = 0;

    for (int k = blockIdx.x; k < K; k += XPB) {
        // warp 0 builds the neighbor list (rank order irrelevant for a sum)
        if (tid < 32) {
            int pk = g_perm[b][k];
            unsigned wd = g_bits1[b][pk][tid];
            int c = __popc(wd);
            int v = c;
            #pragma unroll
            for (int o = 1; o < 32; o <<= 1) {
                int t = __shfl_up_sync(FULL, v, o);
                if (tid >= o) v += t;
            }
            int p = v - c;
            while (wd) {
                int bt = __ffs(wd) - 1;
                wd &= wd - 1;
                list[p++] = tid * 32 + bt;
            }
            if (tid == 31) snn = v;
        }
        __syncthreads();
        int nn = snn;

        size_t xrow = (size_t)b * N;
        if (nn <= DMAL) {
            // DMA gather: nn x-rows (1KB each, contiguous, 16B-aligned) -> smem
            if (tid == 0)
                asm volatile("mbarrier.arrive.expect_tx.shared.b64 _, [%0], %1;"
                             :: "r"(mb), "r"((unsigned)(nn * F * 4)) : "memory");
            __syncthreads();
            if (tid < nn) {
                unsigned dst = smem_addr_of(sm) + tid * (F * 4);
                const char* src = (const char*)(x + (xrow + list[tid]) * F);
                asm volatile(
                    "cp.async.bulk.shared::cluster.global.mbarrier::complete_tx::bytes "
                    "[%0], [%1], %2, [%3];"
                    :: "r"(dst), "l"(src), "r"((unsigned)(F * 4)), "r"(mb) : "memory");
            }
            // pos gather issues BEFORE waiting on x (overlapped)
            float pp = 0.0f;
            if (tid < 96) {
                int c = tid >> 5, l = tid & 31;
                for (int i2 = l; i2 < nn; i2 += 32)
                    pp += __ldg(&pos[(xrow + list[i2]) * 3 + c]);
            }
            // wait for DMA completion (current parity)
            asm volatile(
                "{\n\t.reg .pred P;\n\t.reg .u32 ph;\n\t"
                "mov.u32 ph, %1;\n\t"
                "WX:\n\t"
                "mbarrier.try_wait.parity.shared.b64 P, [%0], ph;\n\t"
                "@!P bra WX;\n\t}"
                :: "r"(mb), "r"((unsigned)par) : "memory");
            par ^= 1;
            // reduce from smem: thread f sums column f over nn rows
            float a0 = 0.f, a1 = 0.f, a2 = 0.f, a3 = 0.f;
            int i = 0;
            for (; i + 3 < nn; i += 4) {
                a0 += sx[(i + 0) * F + tid];
                a1 += sx[(i + 1) * F + tid];
                a2 += sx[(i + 2) * F + tid];
                a3 += sx[(i + 3) * F + tid];
            }
            for (; i < nn; ++i) a0 += sx[i * F + tid];
            out_x[(xrow + k) * F + tid] = (a0 + a1) + (a2 + a3);
            // pos reduce + write
            if (tid < 96) {
                int c = tid >> 5, l = tid & 31;
                #pragma unroll
                for (int o = 16; o; o >>= 1) pp += __shfl_xor_sync(FULL, pp, o);
                if (l == 0) out_pos[(xrow + k) * 3 + c] = pp / (float)nn;
            }
        } else {
            // fallback: direct gather (nn > DMAL; statistically never at deg~32)
            float acc = 0.0f;
            for (int i = 0; i < nn; ++i)
                acc += __ldg(&x[(xrow + list[i]) * F + tid]);
            out_x[(xrow + k) * F + tid] = acc;
            if (tid < 96) {
                int c = tid >> 5, l = tid & 31;
                float pp = 0.0f;
                for (int i2 = l; i2 < nn; i2 += 32)
                    pp += __ldg(&pos[(xrow + list[i2]) * 3 + c]);
                #pragma unroll
                for (int o = 16; o; o >>= 1) pp += __shfl_xor_sync(FULL, pp, o);
                if (l == 0) out_pos[(xrow + k) * 3 + c] = pp / (float)nn;
            }
        }
        __syncthreads();
    }
}

// ---------------- K4: coarsened adjacency, ABLK2 blocks per batch -----------
__global__ void a_kernel(float* __restrict__ out_a) {
    int b = blockIdx.y;
    int ablk = blockIdx.x;                    // 0..ABLK2-1
    int K = g_K[b];
    int tid = threadIdx.x;
    __shared__ unsigned srows[MAXK][33];
    __shared__ int sperm[MAXK];
    int KC = K < MAXK ? K : MAXK;
    for (int j = tid; j < KC; j += 256) sperm[j] = g_perm[b][j];
    __syncthreads();
    for (int t = tid; t < KC * W; t += 256) {
        int j = t >> 5, w = t & 31;
        srows[j][w] = g_bitsA[b][sperm[j]][w];
    }
    __syncthreads();
    for (int i = ablk; i < K; i += ABLK2) {
        int pi = (i < KC) ? sperm[i] : g_perm[b][i];
        const unsigned* ri = (i < KC) ? &srows[i][0] : &g_bitsA[b][pi][0];
        for (int j = tid; j < K; j += 256) {
            const unsigned* rj = (j < KC) ? &srows[j][0] : &g_bitsA[b][g_perm[b][j]][0];
            int s = 0;
            #pragma unroll
            for (int w = 0; w < W; ++w) s += __popc(ri[w] & rj[w]);
            s += (rj[pi >> 5] >> (pi & 31)) & 1;   // diagonal self-term of (A+I)@A
            out_a[((size_t)b * N + i) * N + j] = (float)s;
        }
    }
}

// ---------------- launch ----------------------------------------------------
extern "C" void kernel_launch(void* const* d_in, const int* in_sizes, int n_in,
                              void* d_out, int out_size) {
    const float *x = nullptr, *adj = nullptr, *pos = nullptr, *order = nullptr;
    for (int i = 0; i < n_in; ++i) {
        if      (in_sizes[i] == B * N * N) adj   = (const float*)d_in[i];
        else if (in_sizes[i] == B * N * F) x     = (const float*)d_in[i];
        else if (in_sizes[i] == B * N * 3) pos   = (const float*)d_in[i];
        else if (in_sizes[i] == B * N) { if (!order) order = (const float*)d_in[i]; }
    }
    float* out = (float*)d_out;

    cudaFuncSetAttribute(select_kernel,
                         cudaFuncAttributeMaxDynamicSharedMemorySize, SMEM_SEL_BYTES);
    cudaFuncSetAttribute(xp_kernel,
                         cudaFuncAttributeMaxDynamicSharedMemorySize, SMEM_XP_BYTES);

    pack_zero_rank_kernel<<<TOTAL_BLKS, 256>>>(adj, order, out);
    inc_perm_kernel      <<<(B * N) / 8, 256>>>();
    select_kernel        <<<B, 256, SMEM_SEL_BYTES>>>(out + OFF_M);
    {
        dim3 g(XPB, B);
        xp_kernel<<<g, 256, SMEM_XP_BYTES>>>(x, pos, out + OFF_X, out + OFF_P);
    }
    {
        dim3 g(ABLK2, B);
        a_kernel<<<g, 256>>>(out + OFF_A);
    }
}

// round 17
// speedup vs baseline: 1.1707x; 1.1646x over previous
#include <cuda_runtime.h>
#include <cstdint>

#define B 4
#define N 1024
#define F 256
#define W 32            // 32 x u32 words per 1024-bit row
#define FULL 0xFFFFFFFFu

#define RANK_BLKS 16
#define PACK_BLKS 512   // 512 blocks * 8 warps = 4096 rows
#define K0_BLKS (RANK_BLKS + PACK_BLKS)
#define ZERO_BLKS 512   // zero-fill blocks inside select kernel
#define MAXK 344        // smem row-cache capacity for a_kernel (guarded fallback)
#define MAXL 128        // neighbor-list capacity in xp
#define DMAL 64         // rows DMA-gathered to smem in xp (fallback above)
#define XPB 192         // xp blocks per batch
#define ABLK2 32        // a_kernel blocks per batch
#define RCAP 864        // ranks with SMEM-resident {exc,inc} rows in select

// ---------------- scratch (device globals; no allocations allowed) ----------
__device__ unsigned g_bitsA  [B][N][W];  // adj rows (node space)
__device__ unsigned g_bits1  [B][N][W];  // (adj+I) rows (node space)
__device__ uint2    g_excincR[B][N][W];  // rank-space rows: {exc word, inc word}
__device__ int      g_rank   [B][N];
__device__ int      g_inv    [B][N];
__device__ int      g_perm   [B][N];
__device__ int      g_K      [B];

// Output layout (float32, concatenated):
#define OFF_X   0
#define OFF_P   (B*N*F)
#define OFF_A   (B*N*F + B*N*3)
#define OFF_M   (B*N*F + B*N*3 + B*N*N)
#define NZERO4  ((B*N*F + B*N*3 + B*N*N) / 4)

__device__ __forceinline__ unsigned smem_addr_of(const void* p) {
    unsigned a;
    asm("{ .reg .u64 t; cvta.to.shared.u64 t, %1; cvt.u32.u64 %0, t; }"
        : "=r"(a) : "l"(p));
    return a;
}

// ---------------- K0: rank (blocks 0..15) + pack bitmasks (rest) ------------
__global__ void pack_rank_kernel(const float* __restrict__ adj,
                                 const float* __restrict__ order) {
    if (blockIdx.x < RANK_BLKS) {
        // ---- rank: stable sorted position of order[b][i] (scheduled first) --
        int zb = blockIdx.x;
        int b = zb >> 2;
        int i = (zb & 3) * 256 + threadIdx.x;
        __shared__ float so[N];
        for (int j = threadIdx.x; j < N; j += 256) so[j] = order[b * N + j];
        __syncthreads();
        float oi = so[i];
        int r = 0;
        const float4* s4 = (const float4*)so;
        #pragma unroll 8
        for (int j4 = 0; j4 < N / 4; ++j4) {
            float4 v = s4[j4];
            int j = j4 * 4;
            r += (v.x < oi) || (v.x == oi && (j + 0) < i);
            r += (v.y < oi) || (v.y == oi && (j + 1) < i);
            r += (v.z < oi) || (v.z == oi && (j + 2) < i);
            r += (v.w < oi) || (v.w == oi && (j + 3) < i);
        }
        g_rank[b][i] = r;
        g_inv[b][r] = i;
        return;
    }
    // ---- pack adj rows into bitmasks ----
    int warp = ((blockIdx.x - RANK_BLKS) * blockDim.x + threadIdx.x) >> 5;  // 0..4095
    int lane = threadIdx.x & 31;
    int b = warp >> 10, i = warp & (N - 1);
    const float4* r4 = (const float4*)(adj + ((size_t)b * N + i) * N) + lane * 8;
    unsigned w = 0;
    #pragma unroll
    for (int j = 0; j < 8; ++j) {
        float4 v = r4[j];
        w |= (v.x != 0.f ? 1u : 0u) << (4 * j)
           | (v.y != 0.f ? 1u : 0u) << (4 * j + 1)
           | (v.z != 0.f ? 1u : 0u) << (4 * j + 2)
           | (v.w != 0.f ? 1u : 0u) << (4 * j + 3);
    }
    g_bitsA[b][i][lane] = w;
    unsigned m1 = w | ((lane == (i >> 5)) ? (1u << (i & 31)) : 0u);
    g_bits1[b][i][lane] = m1;
}

// ---------------- K1: inc rows (list-gather, high MLP) + rank permute -------
__global__ void inc_perm_kernel() {
    cudaGridDependencySynchronize();          // PDL: wait for pack+rank data
    int warp = (blockIdx.x * blockDim.x + threadIdx.x) >> 5;
    int wInB = threadIdx.x >> 5;
    int lane = threadIdx.x & 31;
    int b = warp >> 10, i = warp & (N - 1);
    __shared__ int lists[8][64];

    unsigned exc = g_bits1[b][i][lane];
    // compact neighbor node ids into smem list (raises gather MLP)
    int c = __popc(exc);
    int v = c;
    #pragma unroll
    for (int o = 1; o < 32; o <<= 1) {
        int t = __shfl_up_sync(FULL, v, o);
        if (lane >= o) v += t;
    }
    int tot = __shfl_sync(FULL, v, 31);
    int p = v - c;
    unsigned mm = exc;
    while (mm) {
        int bt = __ffs(mm) - 1;
        mm &= mm - 1;
        if (p < 64) lists[wInB][p] = lane * 32 + bt;
        ++p;
    }
    __syncwarp();
    unsigned acc = 0;
    if (tot <= 64) {
        #pragma unroll 4
        for (int t = 0; t < tot; ++t)
            acc |= g_bitsA[b][lists[wInB][t]][lane];
    } else {                                  // statistically-never fallback
        #pragma unroll 4
        for (int w = 0; w < W; ++w) {
            unsigned word = __shfl_sync(FULL, exc, w);
            while (word) {
                int bit = __ffs(word) - 1;
                word &= word - 1;
                acc |= g_bitsA[b][w * 32 + bit][lane];
            }
        }
    }
    // column permutation to rank space
    int sj[32];
    const int4* inv4 = (const int4*)&g_inv[b][0];
    #pragma unroll
    for (int q = 0; q < 8; ++q) {
        int4 vv = inv4[lane * 8 + q];
        sj[4 * q] = vv.x; sj[4 * q + 1] = vv.y; sj[4 * q + 2] = vv.z; sj[4 * q + 3] = vv.w;
    }
    unsigned excw = 0, incw = 0;
    #pragma unroll
    for (int t = 0; t < 32; ++t) {
        int j = sj[t];
        unsigned ew = __shfl_sync(FULL, exc, j >> 5);
        unsigned iw = __shfl_sync(FULL, acc, j >> 5);
        excw |= ((ew >> (j & 31)) & 1u) << t;
        incw |= ((iw >> (j & 31)) & 1u) << t;
    }
    int r = g_rank[b][i];
    g_excincR[b][r][lane] = make_uint2(excw, incw);
}

// ---------------- K2: select (blocks 0..3) + zero-fill (rest, no dep) -------
// dynamic smem: uint2 sEI[RCAP*W] = 864*32*8 = 221184 B
#define SMEM_SEL_BYTES (RCAP * W * 8)
#define BULK_CHUNK (SMEM_SEL_BYTES / 4)       // 55296 B per cp.async.bulk

__global__ void select_zero_kernel(float* __restrict__ out_mask,
                                   float* __restrict__ out_all) {
    if (blockIdx.x >= B) {
        // ---- zero-fill x_p/pos_p/a: independent of prior kernels, NO gridsync
        //      (under PDL these blocks run during inc_perm / select)
        int zb = blockIdx.x - B;
        float4 z = make_float4(0.f, 0.f, 0.f, 0.f);
        float4* o = (float4*)out_all;
        for (int i = zb * blockDim.x + threadIdx.x; i < NZERO4; i += ZERO_BLKS * blockDim.x)
            o[i] = z;
        return;
    }
    cudaGridDependencySynchronize();          // PDL: wait for inc_perm data

    extern __shared__ char sm[];
    uint2* sEI = (uint2*)sm;
    __shared__ unsigned snode[W];
    __shared__ __align__(8) unsigned long long mbar;

    int b = blockIdx.x;
    int tid = threadIdx.x;
    unsigned mb = smem_addr_of(&mbar);
    if (tid == 0)
        asm volatile("mbarrier.init.shared.b64 [%0], 1;" :: "r"(mb) : "memory");
    if (tid < W) snode[tid] = 0;
    __syncthreads();
    if (tid >= 32) return;                    // warp 0 runs everything else
    int lane = tid;

    // DMA staging: 4 bulk copies -> one mbarrier (expect_tx = full size)
    if (lane == 0)
        asm volatile("mbarrier.arrive.expect_tx.shared.b64 _, [%0], %1;"
                     :: "r"(mb), "r"((unsigned)SMEM_SEL_BYTES) : "memory");
    __syncwarp();
    if (lane < 4) {
        unsigned dst = smem_addr_of(sm) + lane * BULK_CHUNK;
        const char* src = (const char*)&g_excincR[b][0][0] + (size_t)lane * BULK_CHUNK;
        asm volatile(
            "cp.async.bulk.shared::cluster.global.mbarrier::complete_tx::bytes "
            "[%0], [%1], %2, [%3];"
            :: "r"(dst), "l"(src), "r"((unsigned)BULK_CHUNK), "r"(mb) : "memory");
    }
    // wait for staging completion (phase 0)
    asm volatile(
        "{\n\t.reg .pred P;\n\t"
        "W0:\n\t"
        "mbarrier.try_wait.parity.shared.b64 P, [%0], 0;\n\t"
        "@!P bra W0;\n\t}"
        :: "r"(mb) : "memory");

    unsigned av = FULL;                       // node_mask all-true
    unsigned sel = 0;                         // rank-space selected set
    unsigned fr = (lane == 0) ? 1u : 0u;      // initial frontier = rank 0
    int r = 0;

    int guard = 0;
    while (guard++ < 2 * N) {
        sel |= (lane == (r >> 5)) ? (1u << (r & 31)) : 0u;
        uint2 ei = (r < RCAP) ? sEI[(r << 5) + lane]    // one LDS.64
                              : g_excincR[b][r][lane];  // rare high-rank fallback
        av &= ~ei.x;                          // exc includes self bit
        fr = (fr | ei.y) & av;
        // branchless: key < N -> frontier pick; N<=key<2N -> restart pick; 2N -> done
        int key = fr ? ((lane << 5) + __ffs(fr) - 1)
                     : (av ? ((lane << 5) + __ffs(av) - 1 + N) : 2 * N);
        key = __reduce_min_sync(FULL, key);
        if (key >= 2 * N) break;              // av empty -> done
        bool restart = key >= N;
        fr = restart ? av : fr;
        r  = restart ? key - N : key;
    }

    // convert rank-space sel to node space
    unsigned m = sel;
    while (m) {
        int t = __ffs(m) - 1;
        m &= m - 1;
        int node = g_inv[b][lane * 32 + t];
        atomicOr(&snode[node >> 5], 1u << (node & 31));
    }
    __syncwarp();
    unsigned selN = snode[lane];

    // stable top_k permutation: selected ascending, then unselected ascending
    int cnt = __popc(selN);
    int v = cnt;
    #pragma unroll
    for (int o = 1; o < 32; o <<= 1) {
        int n2 = __shfl_up_sync(FULL, v, o);
        if (lane >= o) v += n2;
    }
    int K = __shfl_sync(FULL, v, 31);
    int selpos = v - cnt;
    int unspos = K + (lane * 32 - selpos);
    #pragma unroll
    for (int i = 0; i < 32; ++i) {
        int node = lane * 32 + i;
        if ((selN >> i) & 1u) g_perm[b][selpos++] = node;
        else                  g_perm[b][unspos++] = node;
    }
    if (lane == 0) g_K[b] = K;
    #pragma unroll
    for (int w = 0; w < W; ++w) {
        int j = w * 32 + lane;
        out_mask[b * N + j] = (j < K) ? 1.0f : 0.0f;
    }
}

// ---------------- K3: x_p + pos_p via DMA row gather ------------------------
// dynamic smem layout:
//   [0)       float sx[DMAL][F]      65536 B
//   [65536)   int   list[MAXL]         512 B
//   [66048)   u64   mbar                 8 B
#define SMEM_XP_BYTES (65536 + 512 + 16)

__global__ void xp_kernel(const float* __restrict__ x, const float* __restrict__ pos,
                          float* __restrict__ out_x, float* __restrict__ out_pos) {
    extern __shared__ char sm[];
    float* sx  = (float*)sm;
    int* list  = (int*)(sm + 65536);
    unsigned mb = smem_addr_of(sm + 66048);
    __shared__ int snn;

    int b = blockIdx.y;
    int tid = threadIdx.x;
    if (tid == 0)
        asm volatile("mbarrier.init.shared.b64 [%0], 1;" :: "r"(mb) : "memory");
    __syncthreads();
    cudaGridDependencySynchronize();          // PDL: wait for select+zero
    int K = g_K[b];
    int par = 0;

    for (int k = blockIdx.x; k < K; k += XPB) {
        // warp 0 builds the neighbor list
        if (tid < 32) {
            int pk = g_perm[b][k];
            unsigned wd = g_bits1[b][pk][tid];
            int c = __popc(wd);
            int v = c;
            #pragma unroll
            for (int o = 1; o < 32; o <<= 1) {
                int t = __shfl_up_sync(FULL, v, o);
                if (tid >= o) v += t;
            }
            int p = v - c;
            while (wd) {
                int bt = __ffs(wd) - 1;
                wd &= wd - 1;
                list[p++] = tid * 32 + bt;
            }
            if (tid == 31) snn = v;
        }
        __syncthreads();
        int nn = snn;

        size_t xrow = (size_t)b * N;
        if (nn <= DMAL) {
            // DMA gather: nn x-rows (1KB each, 16B-aligned) -> smem
            if (tid == 0)
                asm volatile("mbarrier.arrive.expect_tx.shared.b64 _, [%0], %1;"
                             :: "r"(mb), "r"((unsigned)(nn * F * 4)) : "memory");
            __syncthreads();
            if (tid < nn) {
                unsigned dst = smem_addr_of(sm) + tid * (F * 4);
                const char* src = (const char*)(x + (xrow + list[tid]) * F);
                asm volatile(
                    "cp.async.bulk.shared::cluster.global.mbarrier::complete_tx::bytes "
                    "[%0], [%1], %2, [%3];"
                    :: "r"(dst), "l"(src), "r"((unsigned)(F * 4)), "r"(mb) : "memory");
            }
            // pos gather issues BEFORE waiting on x (overlapped)
            float pp = 0.0f;
            if (tid < 96) {
                int c = tid >> 5, l = tid & 31;
                for (int i2 = l; i2 < nn; i2 += 32)
                    pp += __ldg(&pos[(xrow + list[i2]) * 3 + c]);
            }
            // wait for DMA completion (current parity)
            asm volatile(
                "{\n\t.reg .pred P;\n\t.reg .u32 ph;\n\t"
                "mov.u32 ph, %1;\n\t"
                "WX:\n\t"
                "mbarrier.try_wait.parity.shared.b64 P, [%0], ph;\n\t"
                "@!P bra WX;\n\t}"
                :: "r"(mb), "r"((unsigned)par) : "memory");
            par ^= 1;
            // reduce from smem: thread f sums column f over nn rows
            float a0 = 0.f, a1 = 0.f, a2 = 0.f, a3 = 0.f;
            int i = 0;
            for (; i + 3 < nn; i += 4) {
                a0 += sx[(i + 0) * F + tid];
                a1 += sx[(i + 1) * F + tid];
                a2 += sx[(i + 2) * F + tid];
                a3 += sx[(i + 3) * F + tid];
            }
            for (; i < nn; ++i) a0 += sx[i * F + tid];
            out_x[(xrow + k) * F + tid] = (a0 + a1) + (a2 + a3);
            if (tid < 96) {
                int c = tid >> 5, l = tid & 31;
                #pragma unroll
                for (int o = 16; o; o >>= 1) pp += __shfl_xor_sync(FULL, pp, o);
                if (l == 0) out_pos[(xrow + k) * 3 + c] = pp / (float)nn;
            }
        } else {
            // fallback: direct gather (nn > DMAL; statistically never)
            float acc = 0.0f;
            for (int i = 0; i < nn; ++i)
                acc += __ldg(&x[(xrow + list[i]) * F + tid]);
            out_x[(xrow + k) * F + tid] = acc;
            if (tid < 96) {
                int c = tid >> 5, l = tid & 31;
                float pp = 0.0f;
                for (int i2 = l; i2 < nn; i2 += 32)
                    pp += __ldg(&pos[(xrow + list[i2]) * 3 + c]);
                #pragma unroll
                for (int o = 16; o; o >>= 1) pp += __shfl_xor_sync(FULL, pp, o);
                if (l == 0) out_pos[(xrow + k) * 3 + c] = pp / (float)nn;
            }
        }
        __syncthreads();
    }
}

// ---------------- K4: coarsened adjacency, ABLK2 blocks per batch -----------
__global__ void a_kernel(float* __restrict__ out_a) {
    cudaGridDependencySynchronize();          // PDL: wait for xp (and earlier)
    int b = blockIdx.y;
    int ablk = blockIdx.x;                    // 0..ABLK2-1
    int K = g_K[b];
    int tid = threadIdx.x;
    __shared__ unsigned srows[MAXK][33];
    __shared__ int sperm[MAXK];
    int KC = K < MAXK ? K : MAXK;
    for (int j = tid; j < KC; j += 256) sperm[j] = g_perm[b][j];
    __syncthreads();
    for (int t = tid; t < KC * W; t += 256) {
        int j = t >> 5, w = t & 31;
        srows[j][w] = g_bitsA[b][sperm[j]][w];
    }
    __syncthreads();
    for (int i = ablk; i < K; i += ABLK2) {
        int pi = (i < KC) ? sperm[i] : g_perm[b][i];
        const unsigned* ri = (i < KC) ? &srows[i][0] : &g_bitsA[b][pi][0];
        for (int j = tid; j < K; j += 256) {
            const unsigned* rj = (j < KC) ? &srows[j][0] : &g_bitsA[b][g_perm[b][j]][0];
            int s = 0;
            #pragma unroll
            for (int w = 0; w < W; ++w) s += __popc(ri[w] & rj[w]);
            s += (rj[pi >> 5] >> (pi & 31)) & 1;   // diagonal self-term of (A+I)@A
            out_a[((size_t)b * N + i) * N + j] = (float)s;
        }
    }
}

// ---------------- launch (PDL chain) ----------------------------------------
extern "C" void kernel_launch(void* const* d_in, const int* in_sizes, int n_in,
                              void* d_out, int out_size) {
    const float *x = nullptr, *adj = nullptr, *pos = nullptr, *order = nullptr;
    for (int i = 0; i < n_in; ++i) {
        if      (in_sizes[i] == B * N * N) adj   = (const float*)d_in[i];
        else if (in_sizes[i] == B * N * F) x     = (const float*)d_in[i];
        else if (in_sizes[i] == B * N * 3) pos   = (const float*)d_in[i];
        else if (in_sizes[i] == B * N) { if (!order) order = (const float*)d_in[i]; }
    }
    float* out = (float*)d_out;

    cudaFuncSetAttribute(select_zero_kernel,
                         cudaFuncAttributeMaxDynamicSharedMemorySize, SMEM_SEL_BYTES);
    cudaFuncSetAttribute(xp_kernel,
                         cudaFuncAttributeMaxDynamicSharedMemorySize, SMEM_XP_BYTES);

    cudaLaunchAttribute pdl[1];
    pdl[0].id = cudaLaunchAttributeProgrammaticStreamSerialization;
    pdl[0].val.programmaticStreamSerializationAllowed = 1;

    pack_rank_kernel<<<K0_BLKS, 256>>>(adj, order);

    {
        cudaLaunchConfig_t cfg = {};
        cfg.gridDim = dim3((B * N) / 8);
        cfg.blockDim = dim3(256);
        cfg.attrs = pdl; cfg.numAttrs = 1;
        cudaLaunchKernelEx(&cfg, inc_perm_kernel);
    }
    {
        cudaLaunchConfig_t cfg = {};
        cfg.gridDim = dim3(B + ZERO_BLKS);
        cfg.blockDim = dim3(256);
        cfg.dynamicSmemBytes = SMEM_SEL_BYTES;
        cfg.attrs = pdl; cfg.numAttrs = 1;
        cudaLaunchKernelEx(&cfg, select_zero_kernel,
                           (float*)(out + OFF_M), (float*)(out + OFF_X));
    }
    {
        cudaLaunchConfig_t cfg = {};
        cfg.gridDim = dim3(XPB, B);
        cfg.blockDim = dim3(256);
        cfg.dynamicSmemBytes = SMEM_XP_BYTES;
        cfg.attrs = pdl; cfg.numAttrs = 1;
        cudaLaunchKernelEx(&cfg, xp_kernel,
                           (const float*)x, (const float*)pos,
                           (float*)(out + OFF_X), (float*)(out + OFF_P));
    }
    {
        cudaLaunchConfig_t cfg = {};
        cfg.gridDim = dim3(ABLK2, B);
        cfg.blockDim = dim3(256);
        cfg.attrs = pdl; cfg.numAttrs = 1;
        cudaLaunchKernelEx(&cfg, a_kernel, (float*)(out + OFF_A));
    }
}